// round 6
// baseline (speedup 1.0000x reference)
#include <cuda_runtime.h>
#include <math_constants.h>
#include <cstdint>

#define FMA2(acc, a, w) \
    asm("fma.rn.f32x2 %0, %1, %2, %0;" : "+l"(acc) : "l"(a), "l"(w))
#define FMA2O(dst, a, b_, c_) \
    asm("fma.rn.f32x2 %0, %1, %2, %3;" : "=l"(dst) : "l"(a), "l"(b_), "l"(c_))
#define FMA2S(acc, b_, c_) \
    asm("fma.rn.f32x2 %0, %0, %1, %2;" : "+l"(acc) : "l"(b_), "l"(c_))
#define DUP2(dst, s) \
    asm("mov.b64 %0, {%1, %1};" : "=l"(dst) : "f"(s))
#define MUL2(dst, a, b_) \
    asm("mul.rn.f32x2 %0, %1, %2;" : "=l"(dst) : "l"(a), "l"(b_))
#define UNPK2(lo, hi, s) \
    asm("mov.b64 {%0, %1}, %2;" : "=f"(lo), "=f"(hi) : "l"(s))

// Issue cp.async for one 64-row group (32 floats/row) into an 8 KB swizzled
// stage buffer. rowsLeft >= 1. Caller commits the group.
__device__ __forceinline__
void stage_group(const float* __restrict__ gRowBase, int rowsLeft,
                 float* __restrict__ xb, int lane)
{
    const char* gsrc = (const char*)gRowBase;
    const int maxIdx = rowsLeft * 8 - 1;              // last valid 16B chunk
    #pragma unroll
    for (int k = 0; k < 16; ++k) {
        const int idx = k * 32 + lane;                // 0..511
        const int row = idx >> 3, c = idx & 7;
        const int dstV = row * 8 + (c ^ (row & 7));
        unsigned long long saddr = __cvta_generic_to_shared(xb + dstV * 4);
        const char* src = gsrc + (size_t)min(idx, maxIdx) * 16;
        asm volatile("cp.async.cg.shared.global [%0], [%1], 16;"
                     :: "l"(saddr), "l"(src));
    }
}

// ---------------------------------------------------------------------------
// Single fused kernel. One CTA per batch (256 thr, 8 warps). Each warp sweeps
// nG groups of 64 rows (2 rows/lane) with double-buffered cp.async. Raw
// scores are kept in shared memory; softmax + context finalize in-CTA.
// Dynamic smem: Wk[1024] | scores[S] | 8 warps x 2 x 2048 stage floats.
// ---------------------------------------------------------------------------
__global__ __launch_bounds__(256, 1)
void attn_all(const float* __restrict__ lstm, const float* __restrict__ fh,
              const float* __restrict__ Wq, const float* __restrict__ bq,
              const float* __restrict__ Wk, const float* __restrict__ bk,
              const float* __restrict__ Wv, const float* __restrict__ bv,
              float* __restrict__ out_ctx, float* __restrict__ out_w,
              int S, int nG)
{
    const int b    = blockIdx.x;
    const int tid  = threadIdx.x;
    const int w    = tid >> 5;
    const int lane = tid & 31;

    extern __shared__ __align__(16) float dyn[];
    float* sWk     = dyn;                 // 1024
    float* sScores = dyn + 1024;          // S
    float* sX      = dyn + 1024 + S;      // 8 * 4096

    __shared__ __align__(16) float sQC[32];
    __shared__ __align__(16) float sBk[32];
    __shared__ float sNW[32];
    __shared__ float sCtxW[256], sMw[8], sLw[8], sW1, sM, sInv;

    float* xb0 = sX + w * 4096;           // this warp's two 2048-float bufs
    const size_t rowB = (size_t)b * S;

    // ---- pre-issue group 0 ----
    {
        const int base = w * 64;          // g=0 base for this warp
        if (base < S)
            stage_group(lstm + (rowB + base) * 32, S - base, xb0, lane);
        asm volatile("cp.async.commit_group;");
    }

    // ---- prologue (overlaps group-0 DRAM latency) ----
    ((float4*)sWk)[tid] = ((const float4*)Wk)[tid];
    if (tid < 32) {
        sBk[tid] = bk[tid];
        const float wv = Wv[tid];
        sNW[tid] = -2.f * wv;
        float acc = bq[tid];
        #pragma unroll
        for (int h = 0; h < 32; ++h)
            acc = fmaf(fh[b * 32 + h], Wq[h * 32 + tid], acc);
        sQC[tid] = acc * 2.8853900817779268f;     // * 2*log2(e)
        float t = wv;                              // bv + sum(Wv)
        #pragma unroll
        for (int off = 16; off; off >>= 1)
            t += __shfl_xor_sync(0xffffffffu, t, off);
        if (tid == 0) sW1 = bv[0] + t;
    }
    __syncthreads();

    const float w1 = sW1;
    const ulonglong2* sWkq = (const ulonglong2*)sWk;
    const ulonglong2* sBk2 = (const ulonglong2*)sBk;
    const unsigned long long* qc2 = (const unsigned long long*)sQC;

    unsigned long long Cdup;                       // 2*log2(e)
    DUP2(Cdup, 2.8853900817779268f);

    float m = -CUDART_INF_F, l = 0.f;
    unsigned long long ctx2[16];
    #pragma unroll
    for (int j = 0; j < 16; ++j) ctx2[j] = 0ull;

    // ---- main sweep: nG groups of 64 rows, double-buffered ----
    #pragma unroll 1
    for (int g = 0; g < nG; ++g) {
        if (g + 1 < nG) {
            const int nb = (g + 1) * 512 + w * 64;
            if (nb < S)
                stage_group(lstm + (rowB + nb) * 32, S - nb,
                            xb0 + ((g + 1) & 1) * 2048, lane);
            asm volatile("cp.async.commit_group;");
            asm volatile("cp.async.wait_group 1;");
        } else {
            asm volatile("cp.async.wait_group 0;");
        }
        __syncwarp();

        const int gs = g * 512 + w * 64;
        if (gs >= S) continue;

        const float4* xbuf = (const float4*)(xb0 + (g & 1) * 2048);

        // ---- keys GEMM: rows (gs+lane, gs+32+lane) ----
        unsigned long long acc[2][16];
        #pragma unroll
        for (int j = 0; j < 8; ++j) {
            ulonglong2 t = sBk2[j];
            acc[0][2 * j] = t.x; acc[0][2 * j + 1] = t.y;
            acc[1][2 * j] = t.x; acc[1][2 * j + 1] = t.y;
        }
        #pragma unroll
        for (int jx = 0; jx < 8; ++jx) {
            const int sw = jx ^ (lane & 7);
            float4 xqA = xbuf[lane * 8 + sw];
            float4 xqB = xbuf[(lane + 32) * 8 + sw];
            float xsA[4] = {xqA.x, xqA.y, xqA.z, xqA.w};
            float xsB[4] = {xqB.x, xqB.y, xqB.z, xqB.w};
            #pragma unroll
            for (int i = 0; i < 4; ++i) {
                unsigned long long aA, aB;
                DUP2(aA, xsA[i]);
                DUP2(aB, xsB[i]);
                const int h = jx * 4 + i;
                #pragma unroll
                for (int j2 = 0; j2 < 8; ++j2) {
                    ulonglong2 w2 = sWkq[h * 8 + j2];   // broadcast LDS.128
                    FMA2(acc[0][2 * j2],     aA, w2.x);
                    FMA2(acc[0][2 * j2 + 1], aA, w2.y);
                    FMA2(acc[1][2 * j2],     aB, w2.x);
                    FMA2(acc[1][2 * j2 + 1], aB, w2.y);
                }
            }
        }

        // ---- scores ----
        const bool valid0 = (gs + lane) < S;
        const bool valid1 = (gs + 32 + lane) < S;
        float sc[2];
        #pragma unroll
        for (int r = 0; r < 2; ++r) {
            float s0 = 0.f, s1 = 0.f, s2 = 0.f, s3 = 0.f;
            #pragma unroll
            for (int j = 0; j < 16; ++j) {
                unsigned long long a2;
                FMA2O(a2, acc[r][j], Cdup, qc2[j]);
                float a0, a1;
                UNPK2(a0, a1, a2);
                float e0, e1;
                asm("ex2.approx.f32 %0, %1;" : "=f"(e0) : "f"(a0));
                asm("ex2.approx.f32 %0, %1;" : "=f"(e1) : "f"(a1));
                float r0, r1;
                asm("rcp.approx.f32 %0, %1;" : "=f"(r0) : "f"(e0 + 1.f));
                asm("rcp.approx.f32 %0, %1;" : "=f"(r1) : "f"(e1 + 1.f));
                if (j & 1) { s2 = fmaf(r0, sNW[2 * j], s2); s3 = fmaf(r1, sNW[2 * j + 1], s3); }
                else       { s0 = fmaf(r0, sNW[2 * j], s0); s1 = fmaf(r1, sNW[2 * j + 1], s1); }
            }
            sc[r] = w1 + ((s0 + s1) + (s2 + s3));
        }
        if (!valid0) sc[0] = -CUDART_INF_F;
        if (!valid1) sc[1] = -CUDART_INF_F;

        if (valid0) sScores[gs + lane]      = sc[0];
        if (valid1) sScores[gs + 32 + lane] = sc[1];

        // ---- per-warp online softmax update ----
        float mg = fmaxf(sc[0], sc[1]);
        #pragma unroll
        for (int off = 16; off; off >>= 1)
            mg = fmaxf(mg, __shfl_xor_sync(0xffffffffu, mg, off));

        if (mg > -CUDART_INF_F) {
            const float m_new = fmaxf(m, mg);
            const float c  = (m > -CUDART_INF_F) ? __expf(m - m_new) : 0.f;
            const float p0 = valid0 ? __expf(sc[0] - m_new) : 0.f;
            const float p1 = valid1 ? __expf(sc[1] - m_new) : 0.f;
            l = fmaf(l, c, p0 + p1);
            unsigned long long c2, p0d, p1d;
            DUP2(c2, c); DUP2(p0d, p0); DUP2(p1d, p1);
            #pragma unroll
            for (int j = 0; j < 16; ++j) {
                unsigned long long t;
                MUL2(t, acc[0][j], p0d);
                FMA2(t, acc[1][j], p1d);
                FMA2S(ctx2[j], c2, t);            // ctx = ctx*c + t
            }
            m = m_new;
        }
    }

    // ---- warp-level reduce: l and transpose-reduce ctx ----
    float lw = l;
    #pragma unroll
    for (int off = 16; off; off >>= 1)
        lw += __shfl_xor_sync(0xffffffffu, lw, off);

    float* sR = xb0;                               // free stage buffer, 32x33
    __syncwarp();
    #pragma unroll
    for (int j = 0; j < 16; ++j) {
        float lo, hi;
        UNPK2(lo, hi, ctx2[j]);
        sR[lane * 33 + 2 * j]     = lo;
        sR[lane * 33 + 2 * j + 1] = hi;
    }
    __syncwarp();
    float cs = 0.f;
    #pragma unroll
    for (int l2 = 0; l2 < 32; ++l2)
        cs += sR[l2 * 33 + lane];

    sCtxW[w * 32 + lane] = cs;
    if (lane == 0) { sMw[w] = m; sLw[w] = lw; }
    __syncthreads();

    // ---- cross-warp merge + context output ----
    if (tid < 32) {
        float M = sMw[0];
        #pragma unroll
        for (int ww = 1; ww < 8; ++ww) M = fmaxf(M, sMw[ww]);
        float L = 0.f, ct = 0.f;
        #pragma unroll
        for (int ww = 0; ww < 8; ++ww) {
            const float scw = __expf(sMw[ww] - M);   // 0 for idle warps
            L  = fmaf(sLw[ww], scw, L);
            ct = fmaf(sCtxW[ww * 32 + tid], scw, ct);
        }
        const float invL = 1.f / L;
        out_ctx[b * 32 + tid] = ct * invL;
        if (tid == 0) { sM = M; sInv = invL; }
    }
    __syncthreads();

    // ---- normalize scores smem -> global (single write) ----
    const float M = sM, inv = sInv;
    const int nV4 = S >> 2;
    float4* s4 = (float4*)sScores;
    float4* o4 = (float4*)(out_w + rowB);          // rowB, S multiples of 4
    #pragma unroll 2
    for (int k = tid; k < nV4; k += 256) {
        float4 v = s4[k];
        v.x = __expf(v.x - M) * inv;
        v.y = __expf(v.y - M) * inv;
        v.z = __expf(v.z - M) * inv;
        v.w = __expf(v.w - M) * inv;
        o4[k] = v;
    }
    for (int i = (nV4 << 2) + tid; i < S; i += 256)
        out_w[rowB + i] = __expf(sScores[i] - M) * inv;
}

// ---------------------------------------------------------------------------
extern "C" void kernel_launch(void* const* d_in, const int* in_sizes, int n_in,
                              void* d_out, int out_size)
{
    const float* lstm = (const float*)d_in[0];
    const float* fh   = (const float*)d_in[1];
    const float* Wq   = (const float*)d_in[2];
    const float* bq   = (const float*)d_in[3];
    const float* Wk   = (const float*)d_in[4];
    const float* bk   = (const float*)d_in[5];
    const float* Wv   = (const float*)d_in[6];
    const float* bv   = (const float*)d_in[7];

    const int BH = in_sizes[1];            // B * H
    const int B  = BH / 32;
    const int S  = in_sizes[0] / BH;
    const int nG = (S + 511) / 512;        // 64-row groups per warp

    float* out_ctx = (float*)d_out;                 // [B, 32]
    float* out_w   = out_ctx + (size_t)B * 32;      // [B, S]

    const int smemBytes = (1024 + S + 8 * 4096) * (int)sizeof(float);
    static int attrSet = 0;
    if (!attrSet) {
        cudaFuncSetAttribute(attn_all,
                             cudaFuncAttributeMaxDynamicSharedMemorySize,
                             smemBytes);
        attrSet = 1;
    }

    attn_all<<<B, 256, smemBytes>>>(lstm, fh, Wq, bq, Wk, bk, Wv, bv,
                                    out_ctx, out_w, S, nG);
}

// round 7
// speedup vs baseline: 1.1143x; 1.1143x over previous
#include <cuda_runtime.h>
#include <math_constants.h>
#include <cstdint>

#define C2LOG2E 2.8853900817779268f   // 2*log2(e)

__device__ __forceinline__ void mma_tf32(
    float& d0, float& d1, float& d2, float& d3,
    uint32_t a0, uint32_t a1, uint32_t a2, uint32_t a3,
    uint32_t b0, uint32_t b1)
{
    asm volatile(
        "mma.sync.aligned.m16n8k8.row.col.f32.tf32.tf32.f32 "
        "{%0,%1,%2,%3}, {%4,%5,%6,%7}, {%8,%9}, {%0,%1,%2,%3};"
        : "+f"(d0), "+f"(d1), "+f"(d2), "+f"(d3)
        : "r"(a0), "r"(a1), "r"(a2), "r"(a3), "r"(b0), "r"(b1));
}

// Split fp32 into tf32-exact hi (mask top 10 mantissa bits) + lo remainder.
__device__ __forceinline__ void tf32_split(float x, uint32_t& hi, uint32_t& lo)
{
    hi = __float_as_uint(x) & 0xFFFFE000u;
    lo = __float_as_uint(x - __uint_as_float(hi));
}

// Stage one 64-row group (32 floats/row) into smem at row stride 36 floats.
__device__ __forceinline__
void stage_group(const float* __restrict__ gRowBase, int rowsLeft,
                 float* __restrict__ xb, int lane)
{
    const char* gsrc = (const char*)gRowBase;
    const int maxIdx = rowsLeft * 8 - 1;            // last valid 16B chunk
    #pragma unroll
    for (int k = 0; k < 16; ++k) {
        const int idx = k * 32 + lane;              // 0..511
        const int row = idx >> 3, c = idx & 7;
        unsigned long long saddr =
            __cvta_generic_to_shared(xb + row * 36 + c * 4);
        const char* src = gsrc + (size_t)min(idx, maxIdx) * 16;
        asm volatile("cp.async.cg.shared.global [%0], [%1], 16;"
                     :: "l"(saddr), "l"(src));
    }
}

// ---------------------------------------------------------------------------
// Single fused kernel, one CTA per batch (256 thr, 8 warps). Keys GEMM on
// tensor cores (m16n8k8 tf32, 3xTF32 split); Wk fragments live in registers.
// Epilogue (tanh score, online softmax, context) in mma fragment layout.
// Dynamic smem: scores[S] | 8 warps x 2 x (64 x 36) stage floats.
// ---------------------------------------------------------------------------
__global__ __launch_bounds__(256, 1)
void attn_all(const float* __restrict__ lstm, const float* __restrict__ fh,
              const float* __restrict__ Wq, const float* __restrict__ bq,
              const float* __restrict__ Wk, const float* __restrict__ bk,
              const float* __restrict__ Wv, const float* __restrict__ bv,
              float* __restrict__ out_ctx, float* __restrict__ out_w,
              int S, int nG)
{
    const int b    = blockIdx.x;
    const int tid  = threadIdx.x;
    const int w    = tid >> 5;
    const int lane = tid & 31;
    const int g8   = lane >> 2;          // 0..7  (fragment group)
    const int t4   = lane & 3;           // 0..3  (thread in group)

    extern __shared__ __align__(16) float dyn[];
    float* sScores = dyn;                // S
    float* sX      = dyn + S;            // 8 warps * 2 * 2304

    __shared__ __align__(16) float sQC[32];          // plain query q[d]
    __shared__ float sCtxW[256], sMw[8], sLw[8], sW1, sM, sInv;

    float* xb0 = sX + w * 4608;
    const size_t rowB = (size_t)b * S;

    // ---- prefetch group 0 ----
    {
        const int base = w * 64;
        if (base < S)
            stage_group(lstm + (rowB + base) * 32, S - base, xb0, lane);
        asm volatile("cp.async.commit_group;");
    }

    // ---- prologue: query GEMV (overlaps group-0 DRAM latency) ----
    if (tid < 32) {
        float acc = bq[tid];
        #pragma unroll
        for (int h = 0; h < 32; ++h)
            acc = fmaf(fh[b * 32 + h], Wq[h * 32 + tid], acc);
        sQC[tid] = acc;
        float t = Wv[tid];
        #pragma unroll
        for (int off = 16; off; off >>= 1)
            t += __shfl_xor_sync(0xffffffffu, t, off);
        if (tid == 0) sW1 = bv[0] + t;
    }

    // ---- Wk fragments (hi/lo) into registers: B[k][n] = Wk[k*32+n] ----
    uint32_t Bhi[4][4][2], Blo[4][4][2];
    #pragma unroll
    for (int kt = 0; kt < 4; ++kt)
        #pragma unroll
        for (int nt = 0; nt < 4; ++nt) {
            const int n = nt * 8 + g8;
            const float f0 = Wk[(kt * 8 + t4) * 32 + n];
            const float f1 = Wk[(kt * 8 + t4 + 4) * 32 + n];
            tf32_split(f0, Bhi[kt][nt][0], Blo[kt][nt][0]);
            tf32_split(f1, Bhi[kt][nt][1], Blo[kt][nt][1]);
        }

    __syncthreads();

    // ---- per-lane column constants (8 col-slots) ----
    // slot s -> col = (s>>1)*8 + 2*t4 + (s&1)
    float qck[8], bkc[8], nwv[8];
    #pragma unroll
    for (int s = 0; s < 8; ++s) {
        const int col = (s >> 1) * 8 + 2 * t4 + (s & 1);
        const float bkv = bk[col];
        bkc[s] = bkv;
        nwv[s] = -2.f * Wv[col];
        qck[s] = (sQC[col] + bkv) * C2LOG2E;
    }
    const float w1 = sW1;

    float m = -CUDART_INF_F, l = 0.f;
    float ctx[8];
    #pragma unroll
    for (int s = 0; s < 8; ++s) ctx[s] = 0.f;

    // ---- main sweep ----
    #pragma unroll 1
    for (int gi = 0; gi < nG; ++gi) {
        if (gi + 1 < nG) {
            const int nb = (gi + 1) * 512 + w * 64;
            if (nb < S)
                stage_group(lstm + (rowB + nb) * 32, S - nb,
                            xb0 + ((gi + 1) & 1) * 2304, lane);
            asm volatile("cp.async.commit_group;");
            asm volatile("cp.async.wait_group 1;");
        } else {
            asm volatile("cp.async.wait_group 0;");
        }
        __syncwarp();

        const int gs = gi * 512 + w * 64;
        if (gs >= S) continue;
        const float* xg = xb0 + (gi & 1) * 2304;

        #pragma unroll 1
        for (int mt = 0; mt < 4; ++mt) {
            // ---- GEMM: D[16] = X[mt-tile] @ Wk (3xTF32) ----
            float D[16];
            #pragma unroll
            for (int e = 0; e < 16; ++e) D[e] = 0.f;

            #pragma unroll
            for (int kt = 0; kt < 4; ++kt) {
                const int abase = (mt * 16 + g8) * 36 + kt * 8 + t4;
                const float a0f = xg[abase];
                const float a1f = xg[abase + 288];      // +8 rows
                const float a2f = xg[abase + 4];        // +4 cols
                const float a3f = xg[abase + 292];
                uint32_t ah0, al0, ah1, al1, ah2, al2, ah3, al3;
                tf32_split(a0f, ah0, al0);
                tf32_split(a1f, ah1, al1);
                tf32_split(a2f, ah2, al2);
                tf32_split(a3f, ah3, al3);
                #pragma unroll
                for (int nt = 0; nt < 4; ++nt) {
                    float& d0 = D[nt * 4 + 0];
                    float& d1 = D[nt * 4 + 1];
                    float& d2 = D[nt * 4 + 2];
                    float& d3 = D[nt * 4 + 3];
                    mma_tf32(d0, d1, d2, d3, ah0, ah1, ah2, ah3,
                             Bhi[kt][nt][0], Bhi[kt][nt][1]);
                    mma_tf32(d0, d1, d2, d3, ah0, ah1, ah2, ah3,
                             Blo[kt][nt][0], Blo[kt][nt][1]);
                    mma_tf32(d0, d1, d2, d3, al0, al1, al2, al3,
                             Bhi[kt][nt][0], Bhi[kt][nt][1]);
                }
            }

            // ---- epilogue: rows r0 = gs+mt*16+g8, r1 = r0+8 ----
            const int r0 = gs + mt * 16 + g8;
            const int r1 = r0 + 8;
            const bool v0 = r0 < S, v1 = r1 < S;

            float key[16];
            float s0 = 0.f, s1 = 0.f;
            #pragma unroll
            for (int nt = 0; nt < 4; ++nt)
                #pragma unroll
                for (int c = 0; c < 4; ++c) {
                    const int e = nt * 4 + c;
                    const int s = nt * 2 + (c & 1);
                    const float arg = fmaf(D[e], C2LOG2E, qck[s]);
                    float ex, rc;
                    asm("ex2.approx.f32 %0, %1;" : "=f"(ex) : "f"(arg));
                    asm("rcp.approx.f32 %0, %1;" : "=f"(rc) : "f"(ex + 1.f));
                    if (c < 2) s0 = fmaf(rc, nwv[s], s0);
                    else       s1 = fmaf(rc, nwv[s], s1);
                    key[e] = D[e] + bkc[s];
                }

            // row sums across the 4 lanes of each quad
            s0 += __shfl_xor_sync(0xffffffffu, s0, 1);
            s0 += __shfl_xor_sync(0xffffffffu, s0, 2);
            s1 += __shfl_xor_sync(0xffffffffu, s1, 1);
            s1 += __shfl_xor_sync(0xffffffffu, s1, 2);
            s0 = w1 + s0;
            s1 = w1 + s1;
            if (!v0) s0 = -CUDART_INF_F;
            if (!v1) s1 = -CUDART_INF_F;

            if (t4 == 0) {
                if (v0) sScores[r0] = s0;
                if (v1) sScores[r1] = s1;
            }

            // warp max over this mt's 16 rows
            float mg = fmaxf(s0, s1);
            mg = fmaxf(mg, __shfl_xor_sync(0xffffffffu, mg, 4));
            mg = fmaxf(mg, __shfl_xor_sync(0xffffffffu, mg, 8));
            mg = fmaxf(mg, __shfl_xor_sync(0xffffffffu, mg, 16));

            if (mg > -CUDART_INF_F) {
                const float m_new = fmaxf(m, mg);
                const float cc = (m > -CUDART_INF_F) ? __expf(m - m_new) : 0.f;
                const float p0 = v0 ? __expf(s0 - m_new) : 0.f;
                const float p1 = v1 ? __expf(s1 - m_new) : 0.f;
                l = fmaf(l, cc, p0 + p1);
                #pragma unroll
                for (int nt = 0; nt < 4; ++nt)
                    #pragma unroll
                    for (int bit = 0; bit < 2; ++bit) {
                        const int s = nt * 2 + bit;
                        const float k0 = key[nt * 4 + bit];       // row r0
                        const float k1 = key[nt * 4 + 2 + bit];   // row r1
                        ctx[s] = fmaf(p1, k1, fmaf(p0, k0, ctx[s] * cc));
                    }
                m = m_new;
            }
        }
    }

    // ---- warp-level reduce: l (x4 duplicate across quads) and ctx ----
    #pragma unroll
    for (int off = 16; off; off >>= 1)
        l += __shfl_xor_sync(0xffffffffu, l, off);
    l *= 0.25f;

    #pragma unroll
    for (int s = 0; s < 8; ++s) {
        ctx[s] += __shfl_xor_sync(0xffffffffu, ctx[s], 4);
        ctx[s] += __shfl_xor_sync(0xffffffffu, ctx[s], 8);
        ctx[s] += __shfl_xor_sync(0xffffffffu, ctx[s], 16);
    }
    if (g8 == 0) {                        // lanes 0..3 hold full ctx per col
        #pragma unroll
        for (int s = 0; s < 8; ++s) {
            const int col = (s >> 1) * 8 + 2 * t4 + (s & 1);
            sCtxW[w * 32 + col] = ctx[s];
        }
    }
    if (lane == 0) { sMw[w] = m; sLw[w] = l; }
    __syncthreads();

    // ---- cross-warp merge + context output ----
    if (tid < 32) {
        float M = sMw[0];
        #pragma unroll
        for (int ww = 1; ww < 8; ++ww) M = fmaxf(M, sMw[ww]);
        float L = 0.f, ct = 0.f;
        #pragma unroll
        for (int ww = 0; ww < 8; ++ww) {
            const float scw = __expf(sMw[ww] - M);
            L  = fmaf(sLw[ww], scw, L);
            ct = fmaf(sCtxW[ww * 32 + tid], scw, ct);
        }
        const float invL = 1.f / L;
        out_ctx[b * 32 + tid] = ct * invL;
        if (tid == 0) { sM = M; sInv = invL; }
    }
    __syncthreads();

    // ---- normalize scores smem -> global ----
    const float M = sM, inv = sInv;
    const int nV4 = S >> 2;
    float4* s4 = (float4*)sScores;
    float4* o4 = (float4*)(out_w + rowB);
    #pragma unroll 2
    for (int k = tid; k < nV4; k += 256) {
        float4 v = s4[k];
        v.x = __expf(v.x - M) * inv;
        v.y = __expf(v.y - M) * inv;
        v.z = __expf(v.z - M) * inv;
        v.w = __expf(v.w - M) * inv;
        o4[k] = v;
    }
    for (int i = (nV4 << 2) + tid; i < S; i += 256)
        out_w[rowB + i] = __expf(sScores[i] - M) * inv;
}

// ---------------------------------------------------------------------------
extern "C" void kernel_launch(void* const* d_in, const int* in_sizes, int n_in,
                              void* d_out, int out_size)
{
    const float* lstm = (const float*)d_in[0];
    const float* fh   = (const float*)d_in[1];
    const float* Wq   = (const float*)d_in[2];
    const float* bq   = (const float*)d_in[3];
    const float* Wk   = (const float*)d_in[4];
    const float* bk   = (const float*)d_in[5];
    const float* Wv   = (const float*)d_in[6];
    const float* bv   = (const float*)d_in[7];

    const int BH = in_sizes[1];            // B * H
    const int B  = BH / 32;
    const int S  = in_sizes[0] / BH;
    const int nG = (S + 511) / 512;

    float* out_ctx = (float*)d_out;                 // [B, 32]
    float* out_w   = out_ctx + (size_t)B * 32;      // [B, S]

    const int smemBytes = (S + 8 * 4608) * (int)sizeof(float);
    static int attrSet = 0;
    if (!attrSet) {
        cudaFuncSetAttribute(attn_all,
                             cudaFuncAttributeMaxDynamicSharedMemorySize,
                             smemBytes);
        attrSet = 1;
    }

    attn_all<<<B, 256, smemBytes>>>(lstm, fh, Wq, bq, Wk, bk, Wv, bv,
                                    out_ctx, out_w, S, nG);
}

// round 8
// speedup vs baseline: 1.2328x; 1.1064x over previous
#include <cuda_runtime.h>
#include <math_constants.h>
#include <cstdint>

#define C2LOG2E 2.8853900817779268f    // 2*log2(e)
#define LOG2E   1.4426950408889634f

__device__ __forceinline__ void mma_tf32(
    float& d0, float& d1, float& d2, float& d3,
    uint32_t a0, uint32_t a1, uint32_t a2, uint32_t a3,
    uint32_t b0, uint32_t b1)
{
    asm volatile(
        "mma.sync.aligned.m16n8k8.row.col.f32.tf32.tf32.f32 "
        "{%0,%1,%2,%3}, {%4,%5,%6,%7}, {%8,%9}, {%0,%1,%2,%3};"
        : "+f"(d0), "+f"(d1), "+f"(d2), "+f"(d3)
        : "r"(a0), "r"(a1), "r"(a2), "r"(a3), "r"(b0), "r"(b1));
}

// Split fp32 into tf32-exact hi (top 10 mantissa bits) + lo remainder.
__device__ __forceinline__ void tf32_split(float x, uint32_t& hi, uint32_t& lo)
{
    hi = __float_as_uint(x) & 0xFFFFE000u;
    lo = __float_as_uint(x - __uint_as_float(hi));
}

// Stage one 64-row group (32 floats/row) into smem at row stride 36 floats.
__device__ __forceinline__
void stage_group(const float* __restrict__ gRowBase, int rowsLeft,
                 float* __restrict__ xb, int lane)
{
    const char* gsrc = (const char*)gRowBase;
    const int maxIdx = rowsLeft * 8 - 1;
    #pragma unroll
    for (int k = 0; k < 16; ++k) {
        const int idx = k * 32 + lane;               // 0..511
        const int row = idx >> 3, c = idx & 7;
        unsigned long long saddr =
            __cvta_generic_to_shared(xb + row * 36 + c * 4);
        const char* src = gsrc + (size_t)min(idx, maxIdx) * 16;
        asm volatile("cp.async.cg.shared.global [%0], [%1], 16;"
                     :: "l"(saddr), "l"(src));
    }
}

// ---------------------------------------------------------------------------
// Single fused kernel, one CTA per batch. Keys GEMM on tensor cores
// (m16n8k8 tf32, 3xTF32). NO max-subtraction softmax (scores bounded ~|13|):
// p = exp(score) accumulated directly -> all mt iterations independent.
// sScores holds unnormalized p; final pass multiplies by 1/L.
// ---------------------------------------------------------------------------
__global__ __launch_bounds__(256, 1)
void attn_all(const float* __restrict__ lstm, const float* __restrict__ fh,
              const float* __restrict__ Wq, const float* __restrict__ bq,
              const float* __restrict__ Wk, const float* __restrict__ bk,
              const float* __restrict__ Wv, const float* __restrict__ bv,
              float* __restrict__ out_ctx, float* __restrict__ out_w,
              int S, int nG)
{
    const int b    = blockIdx.x;
    const int tid  = threadIdx.x;
    const int w    = tid >> 5;
    const int lane = tid & 31;
    const int g8   = lane >> 2;           // fragment row group 0..7
    const int t4   = lane & 3;            // thread-in-quad 0..3

    extern __shared__ __align__(16) float dyn[];
    float* sScores = dyn;                 // S  (unnormalized p)
    float* sX      = dyn + S;             // 8 warps * 2 * 2304

    __shared__ __align__(16) float sQC[32];
    __shared__ float sCtxW[256], sLw[8], sW1, sInv;

    float* xb0 = sX + w * 4608;
    const size_t rowB = (size_t)b * S;

    // ---- prefetch group 0 ----
    {
        const int base = w * 64;
        if (base < S)
            stage_group(lstm + (rowB + base) * 32, S - base, xb0, lane);
        asm volatile("cp.async.commit_group;");
    }

    // ---- prologue: query GEMV (overlaps group-0 DRAM latency) ----
    if (tid < 32) {
        float acc = bq[tid];
        #pragma unroll
        for (int h = 0; h < 32; ++h)
            acc = fmaf(fh[b * 32 + h], Wq[h * 32 + tid], acc);
        sQC[tid] = acc;
        float t = Wv[tid];
        #pragma unroll
        for (int off = 16; off; off >>= 1)
            t += __shfl_xor_sync(0xffffffffu, t, off);
        if (tid == 0) sW1 = bv[0] + t;
    }

    // ---- Wk fragments (hi/lo) in registers: B[k][n] = Wk[k*32+n] ----
    uint32_t Bhi[4][4][2], Blo[4][4][2];
    #pragma unroll
    for (int kt = 0; kt < 4; ++kt)
        #pragma unroll
        for (int nt = 0; nt < 4; ++nt) {
            const int n = nt * 8 + g8;
            const float f0 = Wk[(kt * 8 + t4) * 32 + n];
            const float f1 = Wk[(kt * 8 + t4 + 4) * 32 + n];
            tf32_split(f0, Bhi[kt][nt][0], Blo[kt][nt][0]);
            tf32_split(f1, Bhi[kt][nt][1], Blo[kt][nt][1]);
        }

    __syncthreads();

    // ---- per-lane column constants (slot s -> col = (s>>1)*8+2*t4+(s&1)) --
    float qck[8], nwv[8];
    #pragma unroll
    for (int s = 0; s < 8; ++s) {
        const int col = (s >> 1) * 8 + 2 * t4 + (s & 1);
        nwv[s] = -2.f * Wv[col];
        qck[s] = (sQC[col] + bk[col]) * C2LOG2E;
    }
    const float w1l = sW1 * LOG2E;        // exp(score) = exp2(s*log2e + w1l)

    float l = 0.f;
    float ctxD[8];
    #pragma unroll
    for (int s = 0; s < 8; ++s) ctxD[s] = 0.f;

    // ---- main sweep: independent mt tiles, no softmax serial chain ----
    #pragma unroll 1
    for (int gi = 0; gi < nG; ++gi) {
        if (gi + 1 < nG) {
            const int nb = (gi + 1) * 512 + w * 64;
            if (nb < S)
                stage_group(lstm + (rowB + nb) * 32, S - nb,
                            xb0 + ((gi + 1) & 1) * 2304, lane);
            asm volatile("cp.async.commit_group;");
            asm volatile("cp.async.wait_group 1;");
        } else {
            asm volatile("cp.async.wait_group 0;");
        }
        __syncwarp();

        const int gs = gi * 512 + w * 64;
        if (gs >= S) continue;
        const float* xg = xb0 + (gi & 1) * 2304;

        #pragma unroll 1
        for (int mt = 0; mt < 4; ++mt) {
            // ---- GEMM: D[16] = X[mt-tile] @ Wk (3xTF32) ----
            float D[16];
            #pragma unroll
            for (int e = 0; e < 16; ++e) D[e] = 0.f;

            #pragma unroll
            for (int kt = 0; kt < 4; ++kt) {
                const int abase = (mt * 16 + g8) * 36 + kt * 8 + t4;
                uint32_t ah0, al0, ah1, al1, ah2, al2, ah3, al3;
                tf32_split(xg[abase],       ah0, al0);
                tf32_split(xg[abase + 288], ah1, al1);   // +8 rows
                tf32_split(xg[abase + 4],   ah2, al2);   // +4 k
                tf32_split(xg[abase + 292], ah3, al3);
                #pragma unroll
                for (int nt = 0; nt < 4; ++nt) {
                    float& d0 = D[nt * 4 + 0];
                    float& d1 = D[nt * 4 + 1];
                    float& d2 = D[nt * 4 + 2];
                    float& d3 = D[nt * 4 + 3];
                    mma_tf32(d0, d1, d2, d3, ah0, ah1, ah2, ah3,
                             Bhi[kt][nt][0], Bhi[kt][nt][1]);
                    mma_tf32(d0, d1, d2, d3, ah0, ah1, ah2, ah3,
                             Blo[kt][nt][0], Blo[kt][nt][1]);
                    mma_tf32(d0, d1, d2, d3, al0, al1, al2, al3,
                             Bhi[kt][nt][0], Bhi[kt][nt][1]);
                }
            }

            // ---- epilogue: rows r0 = gs+mt*16+g8, r1 = r0+8 ----
            const int r0 = gs + mt * 16 + g8;
            const int r1 = r0 + 8;
            const bool v0 = r0 < S, v1 = r1 < S;

            float s0 = 0.f, s1 = 0.f;
            #pragma unroll
            for (int nt = 0; nt < 4; ++nt)
                #pragma unroll
                for (int c = 0; c < 4; ++c) {
                    const int e = nt * 4 + c;
                    const int s = nt * 2 + (c & 1);
                    const float arg = fmaf(D[e], C2LOG2E, qck[s]);
                    float ex, rc;
                    asm("ex2.approx.f32 %0, %1;" : "=f"(ex) : "f"(arg));
                    asm("rcp.approx.f32 %0, %1;" : "=f"(rc) : "f"(ex + 1.f));
                    if (c < 2) s0 = fmaf(rc, nwv[s], s0);
                    else       s1 = fmaf(rc, nwv[s], s1);
                }

            // quad row-sums (only remaining shuffles in the hot loop)
            s0 += __shfl_xor_sync(0xffffffffu, s0, 1);
            s0 += __shfl_xor_sync(0xffffffffu, s0, 2);
            s1 += __shfl_xor_sync(0xffffffffu, s1, 1);
            s1 += __shfl_xor_sync(0xffffffffu, s1, 2);

            // p = exp(score) directly (scores bounded, no overflow)
            float p0, p1;
            asm("ex2.approx.f32 %0, %1;" : "=f"(p0)
                : "f"(fmaf(s0, LOG2E, w1l)));
            asm("ex2.approx.f32 %0, %1;" : "=f"(p1)
                : "f"(fmaf(s1, LOG2E, w1l)));
            if (!v0) p0 = 0.f;
            if (!v1) p1 = 0.f;

            if (t4 == 0) {
                if (v0) sScores[r0] = p0;
                if (v1) sScores[r1] = p1;
            }

            l += p0 + p1;                    // x4 duplicated across quad
            #pragma unroll
            for (int nt = 0; nt < 4; ++nt)
                #pragma unroll
                for (int bit = 0; bit < 2; ++bit) {
                    const int s = nt * 2 + bit;
                    ctxD[s] = fmaf(p0, D[nt * 4 + bit],
                              fmaf(p1, D[nt * 4 + 2 + bit], ctxD[s]));
                }
        }
    }

    // ---- warp reduce: l (/4 for quad duplication) and ctxD ----
    #pragma unroll
    for (int off = 16; off; off >>= 1)
        l += __shfl_xor_sync(0xffffffffu, l, off);
    l *= 0.25f;

    #pragma unroll
    for (int s = 0; s < 8; ++s) {
        ctxD[s] += __shfl_xor_sync(0xffffffffu, ctxD[s], 4);
        ctxD[s] += __shfl_xor_sync(0xffffffffu, ctxD[s], 8);
        ctxD[s] += __shfl_xor_sync(0xffffffffu, ctxD[s], 16);
    }
    if (g8 == 0) {
        #pragma unroll
        for (int s = 0; s < 8; ++s) {
            const int col = (s >> 1) * 8 + 2 * t4 + (s & 1);
            sCtxW[w * 32 + col] = ctxD[s];
        }
    }
    if (lane == 0) sLw[w] = l;
    __syncthreads();

    // ---- cross-warp merge (plain sums) + context output ----
    if (tid < 32) {
        float L = 0.f, ct = 0.f;
        #pragma unroll
        for (int ww = 0; ww < 8; ++ww) {
            L  += sLw[ww];
            ct += sCtxW[ww * 32 + tid];
        }
        const float invL = 1.f / L;
        out_ctx[b * 32 + tid] = fmaf(ct, invL, bk[tid]);  // + bk fold
        if (tid == 0) sInv = invL;
    }
    __syncthreads();

    // ---- weights = p * (1/L): pure multiply pass ----
    const float inv = sInv;
    const int nV4 = S >> 2;
    float4* s4 = (float4*)sScores;
    float4* o4 = (float4*)(out_w + rowB);
    #pragma unroll 2
    for (int k = tid; k < nV4; k += 256) {
        float4 v = s4[k];
        v.x *= inv; v.y *= inv; v.z *= inv; v.w *= inv;
        o4[k] = v;
    }
    for (int i = (nV4 << 2) + tid; i < S; i += 256)
        out_w[rowB + i] = sScores[i] * inv;
}

// ---------------------------------------------------------------------------
extern "C" void kernel_launch(void* const* d_in, const int* in_sizes, int n_in,
                              void* d_out, int out_size)
{
    const float* lstm = (const float*)d_in[0];
    const float* fh   = (const float*)d_in[1];
    const float* Wq   = (const float*)d_in[2];
    const float* bq   = (const float*)d_in[3];
    const float* Wk   = (const float*)d_in[4];
    const float* bk   = (const float*)d_in[5];
    const float* Wv   = (const float*)d_in[6];
    const float* bv   = (const float*)d_in[7];

    const int BH = in_sizes[1];            // B * H
    const int B  = BH / 32;
    const int S  = in_sizes[0] / BH;
    const int nG = (S + 511) / 512;

    float* out_ctx = (float*)d_out;                 // [B, 32]
    float* out_w   = out_ctx + (size_t)B * 32;      // [B, S]

    const int smemBytes = (S + 8 * 4608) * (int)sizeof(float);
    static int attrSet = 0;
    if (!attrSet) {
        cudaFuncSetAttribute(attn_all,
                             cudaFuncAttributeMaxDynamicSharedMemorySize,
                             smemBytes);
        attrSet = 1;
    }

    attn_all<<<B, 256, smemBytes>>>(lstm, fh, Wq, bq, Wk, bk, Wv, bv,
                                    out_ctx, out_w, S, nG);
}

// round 9
// speedup vs baseline: 1.3192x; 1.0701x over previous
#include <cuda_runtime.h>
#include <math_constants.h>
#include <cstdint>

#define C2LOG2E 2.8853900817779268f    // 2*log2(e)
#define LOG2E   1.4426950408889634f

// Scratch (no allocations allowed): per-(b,chunk) partial L and ctx[32].
__device__ float g_pl[8192];
__device__ float g_pctx[8192 * 32];

__device__ __forceinline__ void mma_tf32(
    float& d0, float& d1, float& d2, float& d3,
    uint32_t a0, uint32_t a1, uint32_t a2, uint32_t a3,
    uint32_t b0, uint32_t b1)
{
    asm volatile(
        "mma.sync.aligned.m16n8k8.row.col.f32.tf32.tf32.f32 "
        "{%0,%1,%2,%3}, {%4,%5,%6,%7}, {%8,%9}, {%0,%1,%2,%3};"
        : "+f"(d0), "+f"(d1), "+f"(d2), "+f"(d3)
        : "r"(a0), "r"(a1), "r"(a2), "r"(a3), "r"(b0), "r"(b1));
}

__device__ __forceinline__ void tf32_split(float x, uint32_t& hi, uint32_t& lo)
{
    hi = __float_as_uint(x) & 0xFFFFE000u;
    lo = __float_as_uint(x - __uint_as_float(hi));
}

// Stage one 64-row group (32 floats/row) into smem at row stride 36 floats.
__device__ __forceinline__
void stage_group(const float* __restrict__ gRowBase, int rowsLeft,
                 float* __restrict__ xb, int lane)
{
    const char* gsrc = (const char*)gRowBase;
    const int maxIdx = rowsLeft * 8 - 1;
    #pragma unroll
    for (int k = 0; k < 16; ++k) {
        const int idx = k * 32 + lane;               // 0..511
        const int row = idx >> 3, c = idx & 7;
        unsigned long long saddr =
            __cvta_generic_to_shared(xb + row * 36 + c * 4);
        const char* src = gsrc + (size_t)min(idx, maxIdx) * 16;
        asm volatile("cp.async.cg.shared.global [%0], [%1], 16;"
                     :: "l"(saddr), "l"(src));
    }
}

// ---------------------------------------------------------------------------
// Kernel 1: grid (nChunk, B), 128 threads, 3 CTAs/SM. Each CTA covers 1024
// rows of one batch; warp sweeps 4 x 64-row groups, double-buffered cp.async.
// Keys GEMM on tensor cores (m16n8k8 tf32, 3xTF32). No-max softmax: p stored
// unnormalized straight to out_w; per-CTA partial (L, ctx[32]) to scratch.
// ---------------------------------------------------------------------------
__global__ __launch_bounds__(128, 3)
void attn_main(const float* __restrict__ lstm, const float* __restrict__ fh,
               const float* __restrict__ Wq, const float* __restrict__ bq,
               const float* __restrict__ Wk, const float* __restrict__ bk,
               const float* __restrict__ Wv, const float* __restrict__ bv,
               float* __restrict__ out_w, int S)
{
    const int chunk = blockIdx.x;
    const int b     = blockIdx.y;
    const int tid   = threadIdx.x;
    const int w     = tid >> 5;
    const int lane  = tid & 31;
    const int g8    = lane >> 2;
    const int t4    = lane & 3;

    extern __shared__ __align__(16) float sX[];      // 4 warps * 2 * 2304

    __shared__ __align__(16) float sQC[32];
    __shared__ float sCtxW[128], sLw[4], sW1;

    float* xb0 = sX + w * 4608;
    const size_t rowB = (size_t)b * S;
    const int cbase = chunk * 1024;

    // ---- prefetch group 0 ----
    {
        const int base = cbase + w * 64;
        if (base < S)
            stage_group(lstm + (rowB + base) * 32, S - base, xb0, lane);
        asm volatile("cp.async.commit_group;");
    }

    // ---- prologue: query GEMV (overlaps group-0 DRAM latency) ----
    if (tid < 32) {
        float acc = bq[tid];
        #pragma unroll
        for (int h = 0; h < 32; ++h)
            acc = fmaf(fh[b * 32 + h], Wq[h * 32 + tid], acc);
        sQC[tid] = acc;
        float t = Wv[tid];
        #pragma unroll
        for (int off = 16; off; off >>= 1)
            t += __shfl_xor_sync(0xffffffffu, t, off);
        if (tid == 0) sW1 = bv[0] + t;
    }

    // ---- Wk fragments (hi/lo) in registers: B[k][n] = Wk[k*32+n] ----
    uint32_t Bhi[4][4][2], Blo[4][4][2];
    #pragma unroll
    for (int kt = 0; kt < 4; ++kt)
        #pragma unroll
        for (int nt = 0; nt < 4; ++nt) {
            const int n = nt * 8 + g8;
            const float f0 = Wk[(kt * 8 + t4) * 32 + n];
            const float f1 = Wk[(kt * 8 + t4 + 4) * 32 + n];
            tf32_split(f0, Bhi[kt][nt][0], Blo[kt][nt][0]);
            tf32_split(f1, Bhi[kt][nt][1], Blo[kt][nt][1]);
        }

    __syncthreads();

    // ---- per-lane column constants (slot s -> col = (s>>1)*8+2*t4+(s&1)) --
    float qck[8], nwv[8];
    #pragma unroll
    for (int s = 0; s < 8; ++s) {
        const int col = (s >> 1) * 8 + 2 * t4 + (s & 1);
        nwv[s] = -2.f * Wv[col];
        qck[s] = (sQC[col] + bk[col]) * C2LOG2E;
    }
    const float w1l = sW1 * LOG2E;

    float l = 0.f;
    float ctxD[8];
    #pragma unroll
    for (int s = 0; s < 8; ++s) ctxD[s] = 0.f;

    // ---- main sweep: 4 groups of 64 rows per warp ----
    #pragma unroll 1
    for (int gi = 0; gi < 4; ++gi) {
        if (gi + 1 < 4) {
            const int nb = cbase + (gi + 1) * 256 + w * 64;
            if (nb < S)
                stage_group(lstm + (rowB + nb) * 32, S - nb,
                            xb0 + ((gi + 1) & 1) * 2304, lane);
            asm volatile("cp.async.commit_group;");
            asm volatile("cp.async.wait_group 1;");
        } else {
            asm volatile("cp.async.wait_group 0;");
        }
        __syncwarp();

        const int gs = cbase + gi * 256 + w * 64;
        if (gs >= S) continue;
        const float* xg = xb0 + (gi & 1) * 2304;

        #pragma unroll 1
        for (int mt = 0; mt < 4; ++mt) {
            // ---- GEMM: D[16] = X[mt-tile] @ Wk (3xTF32) ----
            float D[16];
            #pragma unroll
            for (int e = 0; e < 16; ++e) D[e] = 0.f;

            #pragma unroll
            for (int kt = 0; kt < 4; ++kt) {
                const int abase = (mt * 16 + g8) * 36 + kt * 8 + t4;
                uint32_t ah0, al0, ah1, al1, ah2, al2, ah3, al3;
                tf32_split(xg[abase],       ah0, al0);
                tf32_split(xg[abase + 288], ah1, al1);   // +8 rows
                tf32_split(xg[abase + 4],   ah2, al2);   // +4 k
                tf32_split(xg[abase + 292], ah3, al3);
                #pragma unroll
                for (int nt = 0; nt < 4; ++nt) {
                    float& d0 = D[nt * 4 + 0];
                    float& d1 = D[nt * 4 + 1];
                    float& d2 = D[nt * 4 + 2];
                    float& d3 = D[nt * 4 + 3];
                    mma_tf32(d0, d1, d2, d3, ah0, ah1, ah2, ah3,
                             Bhi[kt][nt][0], Bhi[kt][nt][1]);
                    mma_tf32(d0, d1, d2, d3, ah0, ah1, ah2, ah3,
                             Blo[kt][nt][0], Blo[kt][nt][1]);
                    mma_tf32(d0, d1, d2, d3, al0, al1, al2, al3,
                             Bhi[kt][nt][0], Bhi[kt][nt][1]);
                }
            }

            // ---- epilogue: rows r0 = gs+mt*16+g8, r1 = r0+8 ----
            const int r0 = gs + mt * 16 + g8;
            const int r1 = r0 + 8;
            const bool v0 = r0 < S, v1 = r1 < S;

            float s0 = 0.f, s1 = 0.f;
            #pragma unroll
            for (int nt = 0; nt < 4; ++nt)
                #pragma unroll
                for (int c = 0; c < 4; ++c) {
                    const int e = nt * 4 + c;
                    const int s = nt * 2 + (c & 1);
                    const float arg = fmaf(D[e], C2LOG2E, qck[s]);
                    float ex, rc;
                    asm("ex2.approx.f32 %0, %1;" : "=f"(ex) : "f"(arg));
                    asm("rcp.approx.f32 %0, %1;" : "=f"(rc) : "f"(ex + 1.f));
                    if (c < 2) s0 = fmaf(rc, nwv[s], s0);
                    else       s1 = fmaf(rc, nwv[s], s1);
                }

            s0 += __shfl_xor_sync(0xffffffffu, s0, 1);
            s0 += __shfl_xor_sync(0xffffffffu, s0, 2);
            s1 += __shfl_xor_sync(0xffffffffu, s1, 1);
            s1 += __shfl_xor_sync(0xffffffffu, s1, 2);

            float p0, p1;
            asm("ex2.approx.f32 %0, %1;" : "=f"(p0)
                : "f"(fmaf(s0, LOG2E, w1l)));
            asm("ex2.approx.f32 %0, %1;" : "=f"(p1)
                : "f"(fmaf(s1, LOG2E, w1l)));
            if (!v0) p0 = 0.f;
            if (!v1) p1 = 0.f;

            if (t4 == 0) {                          // unnormalized p -> gmem
                if (v0) out_w[rowB + r0] = p0;
                if (v1) out_w[rowB + r1] = p1;
            }

            l += p0 + p1;
            #pragma unroll
            for (int nt = 0; nt < 4; ++nt)
                #pragma unroll
                for (int bit = 0; bit < 2; ++bit) {
                    const int s = nt * 2 + bit;
                    ctxD[s] = fmaf(p0, D[nt * 4 + bit],
                              fmaf(p1, D[nt * 4 + 2 + bit], ctxD[s]));
                }
        }
    }

    // ---- warp reduce: l (/4 quad dup) and ctxD ----
    #pragma unroll
    for (int off = 16; off; off >>= 1)
        l += __shfl_xor_sync(0xffffffffu, l, off);
    l *= 0.25f;

    #pragma unroll
    for (int s = 0; s < 8; ++s) {
        ctxD[s] += __shfl_xor_sync(0xffffffffu, ctxD[s], 4);
        ctxD[s] += __shfl_xor_sync(0xffffffffu, ctxD[s], 8);
        ctxD[s] += __shfl_xor_sync(0xffffffffu, ctxD[s], 16);
    }
    if (g8 == 0) {
        #pragma unroll
        for (int s = 0; s < 8; ++s) {
            const int col = (s >> 1) * 8 + 2 * t4 + (s & 1);
            sCtxW[w * 32 + col] = ctxD[s];
        }
    }
    if (lane == 0) sLw[w] = l;
    __syncthreads();

    // ---- per-CTA partial out ----
    if (tid < 32) {
        float L = 0.f, ct = 0.f;
        #pragma unroll
        for (int ww = 0; ww < 4; ++ww) {
            L  += sLw[ww];
            ct += sCtxW[ww * 32 + tid];
        }
        const int pc = b * gridDim.x + chunk;
        g_pctx[pc * 32 + tid] = ct;
        if (tid == 0) g_pl[pc] = L;
    }
}

// ---------------------------------------------------------------------------
// Kernel 2: per-b merge of chunk partials -> context output, then normalize
// the unnormalized p row in out_w by 1/L (pure multiply).
// ---------------------------------------------------------------------------
__global__ __launch_bounds__(256)
void attn_finish(const float* __restrict__ bk, float* __restrict__ out_ctx,
                 float* __restrict__ out_w, int S, int nCh)
{
    const int b   = blockIdx.x;
    const int tid = threadIdx.x;

    __shared__ float sInv;

    if (tid < 32) {
        float L = 0.f, ct = 0.f;
        for (int c = 0; c < nCh; ++c) {
            L  += g_pl[b * nCh + c];
            ct += g_pctx[(b * nCh + c) * 32 + tid];
        }
        const float invL = 1.f / L;
        out_ctx[b * 32 + tid] = fmaf(ct, invL, bk[tid]);   // + bk fold
        if (tid == 0) sInv = invL;
    }
    __syncthreads();

    const float inv = sInv;
    const size_t rowB = (size_t)b * S;
    const int nV4 = S >> 2;
    float4* o4 = (float4*)(out_w + rowB);
    #pragma unroll 2
    for (int k = tid; k < nV4; k += 256) {
        float4 v = o4[k];
        v.x *= inv; v.y *= inv; v.z *= inv; v.w *= inv;
        o4[k] = v;
    }
    for (int i = (nV4 << 2) + tid; i < S; i += 256)
        out_w[rowB + i] *= inv;
}

// ---------------------------------------------------------------------------
extern "C" void kernel_launch(void* const* d_in, const int* in_sizes, int n_in,
                              void* d_out, int out_size)
{
    const float* lstm = (const float*)d_in[0];
    const float* fh   = (const float*)d_in[1];
    const float* Wq   = (const float*)d_in[2];
    const float* bq   = (const float*)d_in[3];
    const float* Wk   = (const float*)d_in[4];
    const float* bk   = (const float*)d_in[5];
    const float* Wv   = (const float*)d_in[6];
    const float* bv   = (const float*)d_in[7];

    const int BH = in_sizes[1];            // B * H
    const int B  = BH / 32;
    const int S  = in_sizes[0] / BH;
    const int nCh = (S + 1023) / 1024;     // 1024 rows per CTA

    float* out_ctx = (float*)d_out;                 // [B, 32]
    float* out_w   = out_ctx + (size_t)B * 32;      // [B, S]

    const int smemBytes = 4 * 4608 * (int)sizeof(float);   // 72 KB
    static int attrSet = 0;
    if (!attrSet) {
        cudaFuncSetAttribute(attn_main,
                             cudaFuncAttributeMaxDynamicSharedMemorySize,
                             smemBytes);
        attrSet = 1;
    }

    dim3 grid(nCh, B);
    attn_main<<<grid, 128, smemBytes>>>(lstm, fh, Wq, bq, Wk, bk, Wv, bv,
                                        out_w, S);
    attn_finish<<<B, 256>>>(bk, out_ctx, out_w, S, nCh);
}